// round 8
// baseline (speedup 1.0000x reference)
#include <cuda_runtime.h>
#include <cstdint>

#define BB   16
#define CC   128
#define HH   28
#define WW   28
#define FF   128
#define KK   1152      // CC*9
#define LL   784       // 28*28
#define LPAD 832       // 13*64
#define FT   64
#define LT   64
#define KC   32
#define NKC  (KK/KC)   // 36

// Scratch (allocation-free rule: __device__ globals)
__device__ __align__(16) float g_Pneg[(size_t)BB * KK * LPAD];  // -patches, zero padded
__device__ __align__(16) float g_Wt2[(size_t)KK * 2 * FF];      // W transposed+duplicated [K][2F]

// ---------------- im2col (negated) ----------------
__global__ void __launch_bounds__(256) im2col_kernel(const float* __restrict__ x) {
    const int lp4 = blockIdx.x * 16 + threadIdx.x;
    const int k   = blockIdx.y * 16 + threadIdx.y;
    const int b   = blockIdx.z;
    const int c  = k / 9;
    const int r  = k - c * 9;
    const int kh = r / 3, kw = r - kh * 3;

    const float* xp = x + ((size_t)(b * CC + c)) * (HH * WW);

    float4 v = make_float4(0.f, 0.f, 0.f, 0.f);
    const int l0 = lp4 * 4;
    if (l0 < LL) {
        const int oh  = lp4 / 7;
        const int ow0 = (lp4 - oh * 7) * 4;
        const int ih  = oh + kh - 1;
        if (ih >= 0 && ih < HH) {
            const float* row = xp + ih * WW;
            const int iw0 = ow0 + kw - 1;
            float* vv = reinterpret_cast<float*>(&v);
#pragma unroll
            for (int j = 0; j < 4; j++) {
                int iw = iw0 + j;
                if (iw >= 0 && iw < WW) vv[j] = -row[iw];
            }
        }
    }
    *reinterpret_cast<float4*>(&g_Pneg[((size_t)(b * KK + k)) * LPAD + l0]) = v;
}

// ---------------- W transpose + duplicate ----------------
__global__ void wtrans_kernel(const float* __restrict__ Wg) {
    int idx = blockIdx.x * blockDim.x + threadIdx.x;
    if (idx >= FF * KK) return;
    int k = idx % KK, f = idx / KK;
    float w = Wg[f * KK + k];
    *reinterpret_cast<float2*>(&g_Wt2[(size_t)k * (2 * FF) + 2 * f]) = make_float2(w, w);
}

// ---------------- packed f32x2 helpers ----------------
__device__ __forceinline__ unsigned long long add2(unsigned long long a, unsigned long long b) {
    unsigned long long r;
    asm("add.rn.f32x2 %0, %1, %2;" : "=l"(r) : "l"(a), "l"(b));
    return r;
}
__device__ __forceinline__ void unpack2(unsigned long long v, float& lo, float& hi) {
    unsigned int a, b;
    asm("mov.b64 {%0, %1}, %2;" : "=r"(a), "=r"(b) : "l"(v));
    lo = __uint_as_float(a);
    hi = __uint_as_float(b);
}

#define CPA16(s, g) asm volatile("cp.async.cg.shared.global [%0], [%1], 16;\n" :: "r"(s), "l"(g))

// ---------------- main L1-distance kernel ----------------
// 256 threads/CTA, tile 64f x 64l, per-thread 4f x 4l = 16 terms.
// KC=32 (36 stages), NST=2 double buffer -> smem exactly 48KB.
// sWd: duplicated W [KC][2*FT]; thread tc=tid&15 reads f-pairs {2tc,2tc+1} at byte 16*tc
//      and {2tc+32,2tc+33} at +256B -> 16B lane stride, conflict-free, zero pack MOVs.
// sP:  plain [KC][LT]; tl=(tid>>4)*4 -> LDS.128 broadcast (2 lines/warp).
__global__ void __launch_bounds__(256) adder_kernel(float* __restrict__ out) {
    __shared__ __align__(16) float sWd[2][KC][2 * FT];  // 32 KB
    __shared__ __align__(16) float sP [2][KC][LT];      // 16 KB

    const int tid = threadIdx.x;
    const int b  = blockIdx.z;
    const int f0 = blockIdx.y * FT;
    const int l0 = blockIdx.x * LT;

    const float* gW = g_Wt2 + 2 * f0;                        // [K][2F] slice
    const float* gP = g_Pneg + (size_t)b * KK * LPAD + l0;   // [K][LPAD] slice

    const uint32_t sW_base = (uint32_t)__cvta_generic_to_shared(&sWd[0][0][0]);
    const uint32_t sP_base = (uint32_t)__cvta_generic_to_shared(&sP[0][0][0]);

    // fill (per stage): W tile 32 rows x 128 floats = 1024 float4 -> 4/thread
    //                   P tile 32 rows x  64 floats =  512 float4 -> 2/thread
    const int frow = tid >> 3;           // 0..31
    const int fcw  = (tid & 7) * 4;      // W float4 chunk base (4 consecutive)
    const int fcp  = (tid & 7) * 2;      // P float4 chunk base (2 consecutive)

    auto fill = [&](int s) {
        int bufi = s & 1;
        int k0 = s * KC;
        const float* wr = gW + (size_t)(k0 + frow) * (2 * FF);
        uint32_t wd = sW_base + (uint32_t)(((bufi * KC + frow) * (2 * FT)) * 4);
#pragma unroll
        for (int j = 0; j < 4; j++)
            CPA16(wd + (fcw + j) * 16, wr + (fcw + j) * 4);
        const float* pr = gP + (size_t)(k0 + frow) * LPAD;
        uint32_t pd = sP_base + (uint32_t)(((bufi * KC + frow) * LT) * 4);
#pragma unroll
        for (int j = 0; j < 2; j++)
            CPA16(pd + (fcp + j) * 16, pr + (fcp + j) * 4);
        asm volatile("cp.async.commit_group;\n" ::: "memory");
    };

    const int tc = tid & 15;             // W chunk id -> f = {2tc,2tc+1,2tc+32,2tc+33}
    const int tl = (tid >> 4) * 4;       // 4 consecutive l

    unsigned long long acc[4][2];        // acc[fi][lpair]
#pragma unroll
    for (int i = 0; i < 4; i++) { acc[i][0] = 0ULL; acc[i][1] = 0ULL; }

    const unsigned long long ABSM = 0x7FFFFFFF7FFFFFFFULL;

    fill(0);
    for (int s = 0; s < NKC; s++) {
        asm volatile("cp.async.wait_group 0;\n" ::: "memory");
        __syncthreads();
        if (s + 1 < NKC) fill(s + 1);
        const int buf = s & 1;
#pragma unroll
        for (int kc = 0; kc < KC; kc++) {
            ulonglong2 wA = *reinterpret_cast<const ulonglong2*>(&sWd[buf][kc][4 * tc]);       // (w0,w0),(w1,w1)
            ulonglong2 wB = *reinterpret_cast<const ulonglong2*>(&sWd[buf][kc][4 * tc + 64]);  // (w2,w2),(w3,w3)
            ulonglong2 pv = *reinterpret_cast<const ulonglong2*>(&sP[buf][kc][tl]);            // (p0,p1),(p2,p3) negated
            unsigned long long w[4] = {wA.x, wA.y, wB.x, wB.y};
#pragma unroll
            for (int i = 0; i < 4; i++) {
                unsigned long long d0 = add2(w[i], pv.x) & ABSM;   // |w - p| packed over l
                unsigned long long d1 = add2(w[i], pv.y) & ABSM;
                acc[i][0] = add2(acc[i][0], d0);
                acc[i][1] = add2(acc[i][1], d1);
            }
        }
    }

    // epilogue: out = -sum
    const int lbase = l0 + tl;
    if (lbase < LL) {   // LL % 4 == 0 -> whole float4 valid or invalid
        const int fl[4] = {2 * tc, 2 * tc + 1, 2 * tc + 32, 2 * tc + 33};
#pragma unroll
        for (int i = 0; i < 4; i++) {
            float a0, a1, a2, a3;
            unpack2(acc[i][0], a0, a1);
            unpack2(acc[i][1], a2, a3);
            float4 v = make_float4(-a0, -a1, -a2, -a3);
            *reinterpret_cast<float4*>(&out[((size_t)(b * FF + f0 + fl[i])) * LL + lbase]) = v;
        }
    }
}

extern "C" void kernel_launch(void* const* d_in, const int* in_sizes, int n_in,
                              void* d_out, int out_size) {
    const float* x  = (const float*)d_in[0];   // [16,128,28,28]
    const float* Wg = (const float*)d_in[1];   // [128,128,3,3]
    float* out = (float*)d_out;                // [16,128,28,28]

    dim3 g1(13, 72, 16);
    dim3 b1(16, 16, 1);
    im2col_kernel<<<g1, b1>>>(x);
    wtrans_kernel<<<(FF * KK + 255) / 256, 256>>>(Wg);

    dim3 grid(LPAD / LT /*13*/, FF / FT /*2*/, BB /*16*/);
    adder_kernel<<<grid, 256>>>(out);
}

// round 9
// speedup vs baseline: 1.4449x; 1.4449x over previous
#include <cuda_runtime.h>
#include <cuda_fp16.h>
#include <cstdint>

#define BB   16
#define CC   128
#define HH   28
#define WW   28
#define FF   128
#define KK   1152      // CC*9
#define LL   784       // 28*28
#define LPAD 832       // 13*64
#define FT   64
#define LT   64
#define KC   32
#define NKC  (KK/KC)   // 36

// Scratch (allocation-free rule: __device__ globals)
__device__ __align__(16) __half g_Pneg[(size_t)BB * KK * LPAD];  // -patches (fp16), zero padded
__device__ __align__(16) __half g_Wth[KK * FF];                  // W transposed (fp16) [K][F]

// ---------------- im2col (negated, fp16) ----------------
__global__ void __launch_bounds__(256) im2col_kernel(const float* __restrict__ x) {
    const int lp4 = blockIdx.x * 16 + threadIdx.x;
    const int k   = blockIdx.y * 16 + threadIdx.y;
    const int b   = blockIdx.z;
    const int c  = k / 9;
    const int r  = k - c * 9;
    const int kh = r / 3, kw = r - kh * 3;

    const float* xp = x + ((size_t)(b * CC + c)) * (HH * WW);

    float vv[4] = {0.f, 0.f, 0.f, 0.f};
    const int l0 = lp4 * 4;
    if (l0 < LL) {
        const int oh  = lp4 / 7;
        const int ow0 = (lp4 - oh * 7) * 4;
        const int ih  = oh + kh - 1;
        if (ih >= 0 && ih < HH) {
            const float* row = xp + ih * WW;
            const int iw0 = ow0 + kw - 1;
#pragma unroll
            for (int j = 0; j < 4; j++) {
                int iw = iw0 + j;
                if (iw >= 0 && iw < WW) vv[j] = -row[iw];
            }
        }
    }
    __half2 h0 = __floats2half2_rn(vv[0], vv[1]);
    __half2 h1 = __floats2half2_rn(vv[2], vv[3]);
    uint2 st;
    st.x = *reinterpret_cast<uint32_t*>(&h0);
    st.y = *reinterpret_cast<uint32_t*>(&h1);
    *reinterpret_cast<uint2*>(&g_Pneg[((size_t)(b * KK + k)) * LPAD + l0]) = st;
}

// ---------------- W transpose (fp16) ----------------
__global__ void wtrans_kernel(const float* __restrict__ Wg) {
    int idx = blockIdx.x * blockDim.x + threadIdx.x;
    if (idx >= FF * KK) return;
    int k = idx % KK, f = idx / KK;
    g_Wth[k * FF + f] = __float2half_rn(Wg[f * KK + k]);
}

#define CPA16(s, g) asm volatile("cp.async.cg.shared.global [%0], [%1], 16;\n" :: "r"(s), "l"(g))

// ---------------- main L1-distance kernel (fp16 inner math) ----------------
// 256 threads/CTA, tile 64f x 64l, per-thread 4f x 4l = 16 terms/kc.
// sW/sP: [2][KC][64] halves (128B/row). W read: LDS.64 at 8B lane stride (conflict-free);
// P read: LDS.64 broadcast. hacc flushed to fp32 every 16 k.
__global__ void __launch_bounds__(256) adder_kernel(float* __restrict__ out) {
    __shared__ __align__(16) __half2 sW[2][KC][FT / 2];   // 8 KB
    __shared__ __align__(16) __half2 sP[2][KC][LT / 2];   // 8 KB

    const int tid = threadIdx.x;
    const int b  = blockIdx.z;
    const int f0 = blockIdx.y * FT;
    const int l0 = blockIdx.x * LT;

    const __half* gW = g_Wth + f0;                           // [K][FF] slice
    const __half* gP = g_Pneg + (size_t)b * KK * LPAD + l0;  // [K][LPAD] slice

    const uint32_t sW_base = (uint32_t)__cvta_generic_to_shared(&sW[0][0][0]);
    const uint32_t sP_base = (uint32_t)__cvta_generic_to_shared(&sP[0][0][0]);

    // fill: per stage each tile = 32 rows x 64 halves (128B) = 4KB = 256 x 16B -> 1 chunk/thread
    const int frow = tid >> 3;           // 0..31
    const int fch  = tid & 7;            // 16B chunk (8 halves)

    auto fill = [&](int s) {
        int bufi = s & 1;
        int k0 = s * KC;
        uint32_t wd = sW_base + (uint32_t)(((bufi * KC + frow) * (FT / 2) + fch * 4) * 4);
        CPA16(wd, gW + (size_t)(k0 + frow) * FF + fch * 8);
        uint32_t pd = sP_base + (uint32_t)(((bufi * KC + frow) * (LT / 2) + fch * 4) * 4);
        CPA16(pd, gP + (size_t)(k0 + frow) * LPAD + fch * 8);
        asm volatile("cp.async.commit_group;\n" ::: "memory");
    };

    const int tf2 = (tid & 15) * 2;      // half2 index: f-pairs (4 consecutive f)
    const int tl2 = (tid >> 4) * 2;      // half2 index: l-pairs (4 consecutive l)

    __half2 hacc[4][2];                  // [fi][lpair], fp16 partial (<=16 k-steps)
    float accf[4][4];                    // [fi][l], fp32 running sum
#pragma unroll
    for (int i = 0; i < 4; i++) {
        hacc[i][0] = __float2half2_rn(0.f);
        hacc[i][1] = __float2half2_rn(0.f);
#pragma unroll
        for (int j = 0; j < 4; j++) accf[i][j] = 0.f;
    }

    fill(0);
    for (int s = 0; s < NKC; s++) {
        asm volatile("cp.async.wait_group 0;\n" ::: "memory");
        __syncthreads();
        if (s + 1 < NKC) fill(s + 1);
        const int buf = s & 1;
#pragma unroll
        for (int h16 = 0; h16 < 2; h16++) {
#pragma unroll
            for (int kc = 0; kc < 16; kc++) {
                const int kk = h16 * 16 + kc;
                // (w0,w1),(w2,w3) and (p0,p1),(p2,p3)  [p negated]
                uint2 wu = *reinterpret_cast<const uint2*>(&sW[buf][kk][tf2]);
                uint2 pu = *reinterpret_cast<const uint2*>(&sP[buf][kk][tl2]);
                __half2 w01 = *reinterpret_cast<__half2*>(&wu.x);
                __half2 w23 = *reinterpret_cast<__half2*>(&wu.y);
                __half2 p01 = *reinterpret_cast<__half2*>(&pu.x);
                __half2 p23 = *reinterpret_cast<__half2*>(&pu.y);
                __half2 wd[4] = {__low2half2(w01), __high2half2(w01),
                                 __low2half2(w23), __high2half2(w23)};
#pragma unroll
                for (int i = 0; i < 4; i++) {
                    __half2 d0 = __hadd2(wd[i], p01);   // w - p (p negated)
                    __half2 d1 = __hadd2(wd[i], p23);
                    hacc[i][0] = __hadd2(hacc[i][0], __habs2(d0));
                    hacc[i][1] = __hadd2(hacc[i][1], __habs2(d1));
                }
            }
            // flush fp16 partials to fp32 (every 16 k)
#pragma unroll
            for (int i = 0; i < 4; i++) {
#pragma unroll
                for (int j = 0; j < 2; j++) {
                    float2 t = __half22float2(hacc[i][j]);
                    accf[i][2 * j]     += t.x;
                    accf[i][2 * j + 1] += t.y;
                    hacc[i][j] = __float2half2_rn(0.f);
                }
            }
        }
    }

    // epilogue: out = -sum
    const int tl = (tid >> 4) * 4;
    const int lbase = l0 + tl;
    if (lbase < LL) {   // LL % 4 == 0 -> whole float4 valid or invalid
        const int tf = (tid & 15) * 4;
#pragma unroll
        for (int i = 0; i < 4; i++) {
            float4 v = make_float4(-accf[i][0], -accf[i][1], -accf[i][2], -accf[i][3]);
            int f = f0 + tf + i;
            *reinterpret_cast<float4*>(&out[((size_t)(b * FF + f)) * LL + lbase]) = v;
        }
    }
}

extern "C" void kernel_launch(void* const* d_in, const int* in_sizes, int n_in,
                              void* d_out, int out_size) {
    const float* x  = (const float*)d_in[0];   // [16,128,28,28]
    const float* Wg = (const float*)d_in[1];   // [128,128,3,3]
    float* out = (float*)d_out;                // [16,128,28,28]

    dim3 g1(13, 72, 16);
    dim3 b1(16, 16, 1);
    im2col_kernel<<<g1, b1>>>(x);
    wtrans_kernel<<<(FF * KK + 255) / 256, 256>>>(Wg);

    dim3 grid(LPAD / LT /*13*/, FF / FT /*2*/, BB /*16*/);
    adder_kernel<<<grid, 256>>>(out);
}

// round 10
// speedup vs baseline: 1.5062x; 1.0424x over previous
#include <cuda_runtime.h>
#include <cuda_fp16.h>
#include <cstdint>

#define BB   16
#define CC   128
#define HH   28
#define WW   28
#define FF   128
#define KK   1152      // CC*9
#define LL   784       // 28*28
#define LPAD 832       // 13*64
#define FT   64
#define LT   64
#define KC   32
#define NKC  (KK/KC)   // 36

// Scratch (allocation-free rule: __device__ globals). All values prescaled by 0.25.
__device__ __align__(16) __half g_Pneg[(size_t)BB * KK * LPAD];   // -0.25*patches (fp16), zero padded
__device__ __align__(16) __half g_Wd [(size_t)KK * 2 * FF];       // 0.25*W transposed+duplicated [K][2F]

// ---------------- im2col (negated, prescaled, fp16) ----------------
__global__ void __launch_bounds__(256) im2col_kernel(const float* __restrict__ x) {
    const int lp4 = blockIdx.x * 16 + threadIdx.x;
    const int k   = blockIdx.y * 16 + threadIdx.y;
    const int b   = blockIdx.z;
    const int c  = k / 9;
    const int r  = k - c * 9;
    const int kh = r / 3, kw = r - kh * 3;

    const float* xp = x + ((size_t)(b * CC + c)) * (HH * WW);

    float vv[4] = {0.f, 0.f, 0.f, 0.f};
    const int l0 = lp4 * 4;
    if (l0 < LL) {
        const int oh  = lp4 / 7;
        const int ow0 = (lp4 - oh * 7) * 4;
        const int ih  = oh + kh - 1;
        if (ih >= 0 && ih < HH) {
            const float* row = xp + ih * WW;
            const int iw0 = ow0 + kw - 1;
#pragma unroll
            for (int j = 0; j < 4; j++) {
                int iw = iw0 + j;
                if (iw >= 0 && iw < WW) vv[j] = -0.25f * row[iw];
            }
        }
    }
    __half2 h0 = __floats2half2_rn(vv[0], vv[1]);
    __half2 h1 = __floats2half2_rn(vv[2], vv[3]);
    uint2 st;
    st.x = *reinterpret_cast<uint32_t*>(&h0);
    st.y = *reinterpret_cast<uint32_t*>(&h1);
    *reinterpret_cast<uint2*>(&g_Pneg[((size_t)(b * KK + k)) * LPAD + l0]) = st;
}

// ---------------- W transpose + duplicate (prescaled, fp16) ----------------
__global__ void wtrans_kernel(const float* __restrict__ Wg) {
    int idx = blockIdx.x * blockDim.x + threadIdx.x;
    if (idx >= FF * KK) return;
    int k = idx % KK, f = idx / KK;
    __half h = __float2half_rn(0.25f * Wg[f * KK + k]);
    __half2 d = __halves2half2(h, h);
    *reinterpret_cast<uint32_t*>(&g_Wd[(size_t)k * (2 * FF) + 2 * f]) =
        *reinterpret_cast<uint32_t*>(&d);
}

#define CPA16(s, g) asm volatile("cp.async.cg.shared.global [%0], [%1], 16;\n" :: "r"(s), "l"(g))

// ---------------- main L1-distance kernel (fp16, dup-W) ----------------
// 256 threads/CTA, tile 64f x 64l, per-thread 4f x 4l = 16 terms/kc.
// sWd: dup W [KC][2*FT] halves; thread tc=tid&15 -> one LDS.128 at byte 16*tc
//      yields (w0,w0)..(w3,w3) for f = 4tc..4tc+3. Conflict-free, zero PRMT.
// sP:  [KC][LT] halves; LDS.64 broadcast gives (p0,p1),(p2,p3).
// fp16 partial accumulates a full 32-kc stage (values prescaled by 0.25), then fp32 flush.
__global__ void __launch_bounds__(256) adder_kernel(float* __restrict__ out) {
    __shared__ __align__(16) __half2 sWd[2][KC][FT];      // dup: 2*FT halves = FT half2; 16 KB
    __shared__ __align__(16) __half2 sP [2][KC][LT / 2];  // 8 KB

    const int tid = threadIdx.x;
    const int b  = blockIdx.z;
    const int f0 = blockIdx.y * FT;
    const int l0 = blockIdx.x * LT;

    const __half* gW = g_Wd + 2 * f0;                        // [K][2F] slice
    const __half* gP = g_Pneg + (size_t)b * KK * LPAD + l0;  // [K][LPAD] slice

    const uint32_t sW_base = (uint32_t)__cvta_generic_to_shared(&sWd[0][0][0]);
    const uint32_t sP_base = (uint32_t)__cvta_generic_to_shared(&sP[0][0][0]);

    // fill: W tile/stage = 32 rows x 256B = 512 x16B -> 2 chunks/thread
    //       P tile/stage = 32 rows x 128B = 256 x16B -> 1 chunk/thread
    const int frow = tid >> 3;            // 0..31
    const int fch  = (tid & 7);           // 0..7

    auto fill = [&](int s) {
        int bufi = s & 1;
        int k0 = s * KC;
        const __half* wr = gW + (size_t)(k0 + frow) * (2 * FF);
        uint32_t wd = sW_base + (uint32_t)((bufi * KC + frow) * (FT * 4));  // FT half2 = FT*4 bytes/row
        CPA16(wd + (2 * fch) * 16,     wr + (2 * fch) * 8);
        CPA16(wd + (2 * fch + 1) * 16, wr + (2 * fch + 1) * 8);
        const __half* pr = gP + (size_t)(k0 + frow) * LPAD;
        uint32_t pd = sP_base + (uint32_t)((bufi * KC + frow) * (LT * 2));  // LT/2 half2 = LT*2 bytes/row
        CPA16(pd + fch * 16, pr + fch * 8);
        asm volatile("cp.async.commit_group;\n" ::: "memory");
    };

    const int tc  = tid & 15;             // f = 4tc .. 4tc+3
    const int tl2 = (tid >> 4) * 2;       // half2 index: l = 4*(tid>>4) ..+3

    __half2 hacc[4][2];                   // [fi][lpair], fp16 partial (one stage = 32 k)
    float accf[4][4];                     // [fi][l], fp32 running
#pragma unroll
    for (int i = 0; i < 4; i++) {
        hacc[i][0] = __float2half2_rn(0.f);
        hacc[i][1] = __float2half2_rn(0.f);
#pragma unroll
        for (int j = 0; j < 4; j++) accf[i][j] = 0.f;
    }

    fill(0);
    for (int s = 0; s < NKC; s++) {
        asm volatile("cp.async.wait_group 0;\n" ::: "memory");
        __syncthreads();
        if (s + 1 < NKC) fill(s + 1);
        const int buf = s & 1;
#pragma unroll
        for (int kc = 0; kc < KC; kc++) {
            uint4 wu = *reinterpret_cast<const uint4*>(&sWd[buf][kc][4 * tc]); // 4 dup half2
            uint2 pu = *reinterpret_cast<const uint2*>(&sP[buf][kc][tl2]);     // (p0,p1),(p2,p3)
            __half2 p01 = *reinterpret_cast<__half2*>(&pu.x);
            __half2 p23 = *reinterpret_cast<__half2*>(&pu.y);
            __half2 w[4];
            w[0] = *reinterpret_cast<__half2*>(&wu.x);
            w[1] = *reinterpret_cast<__half2*>(&wu.y);
            w[2] = *reinterpret_cast<__half2*>(&wu.z);
            w[3] = *reinterpret_cast<__half2*>(&wu.w);
#pragma unroll
            for (int i = 0; i < 4; i++) {
                __half2 d0 = __hadd2(w[i], p01);   // w - p (p negated)
                __half2 d1 = __hadd2(w[i], p23);
                hacc[i][0] = __hadd2(hacc[i][0], __habs2(d0));
                hacc[i][1] = __hadd2(hacc[i][1], __habs2(d1));
            }
        }
        // flush fp16 partials to fp32 once per stage
#pragma unroll
        for (int i = 0; i < 4; i++) {
#pragma unroll
            for (int j = 0; j < 2; j++) {
                float2 t = __half22float2(hacc[i][j]);
                accf[i][2 * j]     += t.x;
                accf[i][2 * j + 1] += t.y;
                hacc[i][j] = __float2half2_rn(0.f);
            }
        }
    }

    // epilogue: out = -4 * sum (undo 0.25 prescale)
    const int tl = (tid >> 4) * 4;
    const int lbase = l0 + tl;
    if (lbase < LL) {   // LL % 4 == 0 -> whole float4 valid or invalid
#pragma unroll
        for (int i = 0; i < 4; i++) {
            float4 v = make_float4(-4.f * accf[i][0], -4.f * accf[i][1],
                                   -4.f * accf[i][2], -4.f * accf[i][3]);
            int f = f0 + 4 * tc + i;
            *reinterpret_cast<float4*>(&out[((size_t)(b * FF + f)) * LL + lbase]) = v;
        }
    }
}

extern "C" void kernel_launch(void* const* d_in, const int* in_sizes, int n_in,
                              void* d_out, int out_size) {
    const float* x  = (const float*)d_in[0];   // [16,128,28,28]
    const float* Wg = (const float*)d_in[1];   // [128,128,3,3]
    float* out = (float*)d_out;                // [16,128,28,28]

    dim3 g1(13, 72, 16);
    dim3 b1(16, 16, 1);
    im2col_kernel<<<g1, b1>>>(x);
    wtrans_kernel<<<(FF * KK + 255) / 256, 256>>>(Wg);

    dim3 grid(LPAD / LT /*13*/, FF / FT /*2*/, BB /*16*/);
    adder_kernel<<<grid, 256>>>(out);
}